// round 8
// baseline (speedup 1.0000x reference)
#include <cuda_runtime.h>
#include <cstdint>

// Problem constants (fixed by the reference setup_inputs)
static constexpr int B = 256;
static constexpr int R = 36;
static constexpr int T = 64;
static constexpr int D = 1024;

static constexpr int CHUNK  = 128;   // d-elements staged per smem tile
static constexpr int NCHUNK = D / CHUNK;   // 8
static constexpr int STRIDE = CHUNK + 4;   // 132 words: 132 % 32 == 4 -> conflict-free LDS.128 tiling

// Shared-memory layout (float offsets)
static constexpr int OFF_CAP  = 0;                        // 64*132 = 8448
static constexpr int OFF_IMG  = OFF_CAP + T * STRIDE;     // 8448 + 36*132 = 13200
static constexpr int OFF_PART = OFF_IMG + R * STRIDE;     // 13200; 4*64*37 = 9472
static constexpr int OFF_DOTS = OFF_PART + 4 * T * 37;    // 22672; 64*37 = 2368
static constexpr int OFF_NORM = OFF_DOTS + T * 37;        // 25040; 128
static constexpr int SMEM_FLOATS = OFF_NORM + 128;        // 25168 floats = 100672 bytes
static constexpr int SMEM_BYTES  = SMEM_FLOATS * 4;

// ---- packed fp32x2 helpers (sm_100+ packed fp32 pipe; ptxas never auto-fuses) ----
#define FMA2(acc, a, b) \
    asm("fma.rn.f32x2 %0, %1, %2, %0;" : "+l"(acc) : "l"(a), "l"(b))

__device__ __forceinline__ long long packf2(float lo, float hi) {
    long long v;
    asm("mov.b64 %0, {%1, %2};" : "=l"(v) : "r"(__float_as_uint(lo)), "r"(__float_as_uint(hi)));
    return v;
}
__device__ __forceinline__ void unpackf2(long long v, float& lo, float& hi) {
    unsigned int a, b2;
    asm("mov.b64 {%0, %1}, %2;" : "=r"(a), "=r"(b2) : "l"(v));
    lo = __uint_as_float(a);
    hi = __uint_as_float(b2);
}
__device__ __forceinline__ float sumf2(long long v) {
    float lo, hi;
    unpackf2(v, lo, hi);
    return lo + hi;
}

extern "C" __global__ void __launch_bounds__(256, 2)
scan_fused_kernel(const float* __restrict__ img,
                  const float* __restrict__ cap,
                  float* __restrict__ out)
{
    extern __shared__ float sm[];
    float* capS = sm + OFF_CAP;    // [t][STRIDE]
    float* imgS = sm + OFF_IMG;    // [r][STRIDE]
    float* part = sm + OFF_PART;   // [dq][t][37]
    float* dots = sm + OFF_DOTS;   // [t][37]
    float* nrm  = sm + OFF_NORM;   // [0..35]=img norms, [36..99]=cap norms
    long long* attn2 = reinterpret_cast<long long*>(sm + OFF_PART);  // alias (part is dead)

    const int b    = blockIdx.x;
    const int tid  = threadIdx.x;
    const int warp = tid >> 5;
    const int lane = tid & 31;
    const int tg   = warp >> 2;            // 0..1 : t-half
    const int dq   = warp & 3;             // 0..3 : d-quarter within each chunk
    const int myT  = (tg << 5) | lane;     // 0..63 : lane <-> t (conflict-free cap LDS)

    const float* gImg = img + (size_t)b * R * D;
    const float* gCap = cap + (size_t)b * T * D;
    float*       gOut = out + (size_t)b * T * D;

    // ---------------- Phase A: dots[r][t] over d (split-K by warp dq) ----------------
    long long acc2[R];                     // packed (even-d, odd-d) partial dots
#pragma unroll
    for (int r = 0; r < R; r++) acc2[r] = 0;
    float normAcc = 0.f;

#pragma unroll 1
    for (int c = 0; c < NCHUNK; c++) {
        const int d0 = c * CHUNK;

        // stage cap tile: 64 rows x 32 float4 (coalesced 512B/warp reads, conflict-free STS.128)
#pragma unroll 1
        for (int i4 = tid; i4 < T * 32; i4 += 256) {
            int t = i4 >> 5, d4 = i4 & 31;
            float4 v = *(const float4*)(gCap + (size_t)t * D + d0 + 4 * d4);
            *(float4*)(capS + t * STRIDE + 4 * d4) = v;
        }
        // stage img tile: 36 rows x 32 float4
#pragma unroll 1
        for (int i4 = tid; i4 < R * 32; i4 += 256) {
            int r = i4 >> 5, d4 = i4 & 31;
            float4 v = *(const float4*)(gImg + (size_t)r * D + d0 + 4 * d4);
            *(float4*)(imgS + r * STRIDE + 4 * d4) = v;
        }
        __syncthreads();

        // fused norm accumulation from the smem tiles (no extra HBM pass)
        if (tid < R + T) {
            const float* row = (tid < R) ? (imgS + tid * STRIDE)
                                         : (capS + (tid - R) * STRIDE);
#pragma unroll
            for (int k = 0; k < 32; k++) {
                float4 v = *(const float4*)(row + 4 * k);
                normAcc += v.x * v.x + v.y * v.y + v.z * v.z + v.w * v.w;
            }
        }

        // dot accumulation: this warp covers d in [dq*32, dq*32+32) of the chunk
        const float* capRow = capS + myT * STRIDE + dq * 32;
        const float* imgCol = imgS + dq * 32;
#pragma unroll 1
        for (int j = 0; j < 8; j++) {
            longlong2 c2 = *(const longlong2*)(capRow + 4 * j);  // conflict-free LDS.128
            const float* ip = imgCol + 4 * j;
#pragma unroll
            for (int r = 0; r < R; r++) {
                longlong2 i2 = *(const longlong2*)(ip + r * STRIDE);  // broadcast LDS.128
                FMA2(acc2[r], i2.x, c2.x);
                FMA2(acc2[r], i2.y, c2.y);
            }
        }
        __syncthreads();
    }

    // write split-K partials (stride 37 -> conflict-free STS)
    {
        float* pp = part + dq * (T * 37) + myT * 37;
#pragma unroll
        for (int r = 0; r < R; r++) pp[r] = sumf2(acc2[r]);
    }
    if (tid < R + T) nrm[tid] = sqrtf(normAcc);
    __syncthreads();

    // ---------------- reduce partials -> dots ----------------
#pragma unroll 1
    for (int idx = tid; idx < R * T; idx += 256) {
        int t = idx / R, r = idx - t * R;
        int o = t * 37 + r;
        dots[o] = part[o] + part[T * 37 + o] + part[2 * T * 37 + o] + part[3 * T * 37 + o];
    }
    __syncthreads();

    // ---------------- Phase B: cosine scale + softmax over r (one thread per t) ----------------
    // writes attn2 (aliases the now-dead partials buffer) as pre-duplicated f32x2
    if (tid < T) {
        const float cn = nrm[R + tid];
        float s[R];
        float m = -1e30f;
#pragma unroll
        for (int r = 0; r < R; r++) {
            float denom = fmaxf(nrm[r] * cn, 1e-8f);
            s[r] = dots[tid * 37 + r] / denom;
            m = fmaxf(m, s[r]);
        }
        float sum = 0.f;
#pragma unroll
        for (int r = 0; r < R; r++) { s[r] = expf(s[r] - m); sum += s[r]; }
        float inv = 1.f / sum;
#pragma unroll
        for (int r = 0; r < R; r++) {
            float a = s[r] * inv;
            attn2[tid * R + r] = packf2(a, a);
        }
    }
    __syncthreads();

    // ---------------- Phase C: out[t][d] = sum_r attn[r][t] * img[r][d] ----------------
    // warp <-> 8-t group (attn loads are warp-uniform LDS.64 broadcasts),
    // lane <-> d-float4 (img LDG.128 perfectly coalesced, 512B/warp, L2-resident)
    {
        const int tt = warp;          // 0..7 -> t in [8*tt, 8*tt+8)
        const int dd = lane;          // 0..31
        const long long* at = attn2 + (tt * 8) * R;
#pragma unroll 1
        for (int it = 0; it < 8; it++) {
            const int d4 = dd + 32 * it;
            long long accA[8], accB[8];
#pragma unroll
            for (int s_ = 0; s_ < 8; s_++) { accA[s_] = 0; accB[s_] = 0; }
#pragma unroll 6
            for (int r = 0; r < R; r++) {
                longlong2 i2 = *(const longlong2*)(gImg + (size_t)r * D + 4 * d4);
#pragma unroll
                for (int s_ = 0; s_ < 8; s_++) {
                    long long a = at[s_ * R + r];
                    FMA2(accA[s_], i2.x, a);
                    FMA2(accB[s_], i2.y, a);
                }
            }
#pragma unroll
            for (int s_ = 0; s_ < 8; s_++) {
                float4 o;
                unpackf2(accA[s_], o.x, o.y);
                unpackf2(accB[s_], o.z, o.w);
                *(float4*)(gOut + (size_t)(tt * 8 + s_) * D + 4 * d4) = o;
            }
        }
    }
}

extern "C" void kernel_launch(void* const* d_in, const int* in_sizes, int n_in,
                              void* d_out, int out_size)
{
    const float* img = (const float*)d_in[0];   // (B, R, D) fp32
    const float* cap = (const float*)d_in[1];   // (B, T, D) fp32
    // d_in[2] = cap_mask, unused by the reference forward
    float* out = (float*)d_out;                 // (B, T, D) fp32

    // idempotent, non-stream API: safe under graph capture
    cudaFuncSetAttribute(scan_fused_kernel,
                         cudaFuncAttributeMaxDynamicSharedMemorySize, SMEM_BYTES);

    scan_fused_kernel<<<B, 256, SMEM_BYTES>>>(img, cap, out);
}

// round 10
// speedup vs baseline: 1.0240x; 1.0240x over previous
#include <cuda_runtime.h>
#include <cstdint>

// Problem constants (fixed by the reference setup_inputs)
static constexpr int B = 256;
static constexpr int R = 36;
static constexpr int T = 64;
static constexpr int D = 1024;

static constexpr int CHUNK  = 128;         // d-elements staged per smem tile
static constexpr int NCHUNK = D / CHUNK;   // 8
static constexpr int STRIDE = CHUNK + 4;   // 132 words -> conflict-free LDS.128 tiling

// Shared-memory layout (float offsets)
static constexpr int OFF_CAP  = 0;                        // 64*132 = 8448
static constexpr int OFF_IMG  = OFF_CAP + T * STRIDE;     // +36*132 = 4752
static constexpr int OFF_PART = OFF_IMG + R * STRIDE;     // 13200; 2*64*37 = 4736
static constexpr int OFF_DOTS = OFF_PART + 2 * T * 37;    // 17936; 64*37 = 2368
static constexpr int OFF_NORM = OFF_DOTS + T * 37;        // 20304; 128
static constexpr int SMEM_FLOATS = OFF_NORM + 128;        // 20432 floats = 81728 bytes
static constexpr int SMEM_BYTES  = SMEM_FLOATS * 4;

static constexpr int RH = R / 2;           // 18 accumulators per warp (was 36 -> spilled)

// ---- packed fp32x2 helpers (sm_100+ packed fp32 pipe; ptxas never auto-fuses) ----
#define FMA2(acc, a, b) \
    asm("fma.rn.f32x2 %0, %1, %2, %0;" : "+l"(acc) : "l"(a), "l"(b))

__device__ __forceinline__ long long packf2(float lo, float hi) {
    long long v;
    asm("mov.b64 %0, {%1, %2};" : "=l"(v) : "r"(__float_as_uint(lo)), "r"(__float_as_uint(hi)));
    return v;
}
__device__ __forceinline__ void unpackf2(long long v, float& lo, float& hi) {
    unsigned int a, b2;
    asm("mov.b64 {%0, %1}, %2;" : "=r"(a), "=r"(b2) : "l"(v));
    lo = __uint_as_float(a);
    hi = __uint_as_float(b2);
}
__device__ __forceinline__ float sumf2(long long v) {
    float lo, hi;
    unpackf2(v, lo, hi);
    return lo + hi;
}

extern "C" __global__ void __launch_bounds__(256, 2)
scan_fused_kernel(const float* __restrict__ img,
                  const float* __restrict__ cap,
                  float* __restrict__ out)
{
    extern __shared__ float sm[];
    float* capS = sm + OFF_CAP;    // [t][STRIDE]
    float* imgS = sm + OFF_IMG;    // [r][STRIDE]
    float* part = sm + OFF_PART;   // [dh][t][37]
    float* dots = sm + OFF_DOTS;   // [t][37]
    float* nrm  = sm + OFF_NORM;   // [0..35]=img norms, [36..99]=cap norms
    long long* attn2 = reinterpret_cast<long long*>(sm + OFF_PART);  // alias (part dead after reduce)

    const int b    = blockIdx.x;
    const int tid  = threadIdx.x;
    const int warp = tid >> 5;
    const int lane = tid & 31;
    const int tg   = warp & 1;             // t-half
    const int rh   = (warp >> 1) & 1;      // r-half  (halves the accumulator count)
    const int dh   = (warp >> 2) & 1;      // d-half  (split-K of 2)
    const int myT  = (tg << 5) | lane;     // lane <-> t : conflict-free cap LDS

    const float* gImg = img + (size_t)b * R * D;
    const float* gCap = cap + (size_t)b * T * D;
    float*       gOut = out + (size_t)b * T * D;

    // ---------------- Phase A: dots[r][t] over d ----------------
    long long acc2[RH];                    // 18 packed (even-d, odd-d) partial dots = 36 regs
#pragma unroll
    for (int rr = 0; rr < RH; rr++) acc2[rr] = 0;
    float normAcc = 0.f;

#pragma unroll 1
    for (int c = 0; c < NCHUNK; c++) {
        const int d0 = c * CHUNK;

        // stage cap tile: 64 rows x 32 float4 (coalesced LDG.128, conflict-free STS.128)
#pragma unroll 1
        for (int i4 = tid; i4 < T * 32; i4 += 256) {
            int t = i4 >> 5, d4 = i4 & 31;
            float4 v = *(const float4*)(gCap + (size_t)t * D + d0 + 4 * d4);
            *(float4*)(capS + t * STRIDE + 4 * d4) = v;
        }
        // stage img tile: 36 rows x 32 float4
#pragma unroll 1
        for (int i4 = tid; i4 < R * 32; i4 += 256) {
            int r = i4 >> 5, d4 = i4 & 31;
            float4 v = *(const float4*)(gImg + (size_t)r * D + d0 + 4 * d4);
            *(float4*)(imgS + r * STRIDE + 4 * d4) = v;
        }
        __syncthreads();

        // fused norm accumulation from the smem tiles (no extra HBM pass)
        if (tid < R + T) {
            const float* row = (tid < R) ? (imgS + tid * STRIDE)
                                         : (capS + (tid - R) * STRIDE);
#pragma unroll
            for (int k = 0; k < 32; k++) {
                float4 v = *(const float4*)(row + 4 * k);
                normAcc += v.x * v.x + v.y * v.y + v.z * v.z + v.w * v.w;
            }
        }

        // dot accumulation: this warp covers d in [dh*64, dh*64+64), r in [rh*18, rh*18+18)
        const float* capRow  = capS + myT * STRIDE + dh * 64;
        const float* imgBase = imgS + (rh * RH) * STRIDE + dh * 64;
#pragma unroll 2
        for (int j = 0; j < 16; j++) {
            longlong2 c2 = *(const longlong2*)(capRow + 4 * j);   // conflict-free LDS.128
            const float* ip = imgBase + 4 * j;
#pragma unroll
            for (int rr = 0; rr < RH; rr++) {
                longlong2 i2 = *(const longlong2*)(ip + rr * STRIDE);  // broadcast LDS.128
                FMA2(acc2[rr], i2.x, c2.x);
                FMA2(acc2[rr], i2.y, c2.y);
            }
        }
        __syncthreads();
    }

    // write split-K partials: r-halves are disjoint columns, d-halves are the 2 reduce planes
    {
        float* pp = part + dh * (T * 37) + myT * 37 + rh * RH;
#pragma unroll
        for (int rr = 0; rr < RH; rr++) pp[rr] = sumf2(acc2[rr]);
    }
    if (tid < R + T) nrm[tid] = sqrtf(normAcc);
    __syncthreads();

    // ---------------- reduce d-half partials -> dots ----------------
#pragma unroll 1
    for (int idx = tid; idx < R * T; idx += 256) {
        int t = idx / R, r = idx - t * R;
        int o = t * 37 + r;
        dots[o] = part[o] + part[T * 37 + o];
    }
    __syncthreads();

    // ---------------- Phase B: cosine scale + softmax over r (one thread per t) ----------------
    if (tid < T) {
        const float cn = nrm[R + tid];
        float s[R];
        float m = -1e30f;
#pragma unroll
        for (int r = 0; r < R; r++) {
            float denom = fmaxf(nrm[r] * cn, 1e-8f);
            s[r] = dots[tid * 37 + r] / denom;
            m = fmaxf(m, s[r]);
        }
        float sum = 0.f;
#pragma unroll
        for (int r = 0; r < R; r++) { s[r] = expf(s[r] - m); sum += s[r]; }
        float inv = 1.f / sum;
#pragma unroll
        for (int r = 0; r < R; r++) {
            float a = s[r] * inv;
            attn2[tid * R + r] = packf2(a, a);   // pre-duplicated for Phase C FMA2
        }
    }
    __syncthreads();

    // ---------------- Phase C: out[t][d] = sum_r attn[r][t] * img[r][d] ----------------
    // warp <-> 8-t group (attn loads are warp-uniform LDS.64 broadcasts),
    // lane <-> d-float4 (img LDG.128 perfectly coalesced, L2-resident)
    {
        const int tt = warp;
        const int dd = lane;
        const long long* at = attn2 + (tt * 8) * R;
#pragma unroll 1
        for (int it = 0; it < 8; it++) {
            const int d4 = dd + 32 * it;
            long long accA[8], accB[8];
#pragma unroll
            for (int s_ = 0; s_ < 8; s_++) { accA[s_] = 0; accB[s_] = 0; }
#pragma unroll 6
            for (int r = 0; r < R; r++) {
                longlong2 i2 = *(const longlong2*)(gImg + (size_t)r * D + 4 * d4);
#pragma unroll
                for (int s_ = 0; s_ < 8; s_++) {
                    long long a = at[s_ * R + r];
                    FMA2(accA[s_], i2.x, a);
                    FMA2(accB[s_], i2.y, a);
                }
            }
#pragma unroll
            for (int s_ = 0; s_ < 8; s_++) {
                float4 o;
                unpackf2(accA[s_], o.x, o.y);
                unpackf2(accB[s_], o.z, o.w);
                *(float4*)(gOut + (size_t)(tt * 8 + s_) * D + 4 * d4) = o;
            }
        }
    }
}

extern "C" void kernel_launch(void* const* d_in, const int* in_sizes, int n_in,
                              void* d_out, int out_size)
{
    const float* img = (const float*)d_in[0];   // (B, R, D) fp32
    const float* cap = (const float*)d_in[1];   // (B, T, D) fp32
    // d_in[2] = cap_mask, unused by the reference forward
    float* out = (float*)d_out;                 // (B, T, D) fp32

    cudaFuncSetAttribute(scan_fused_kernel,
                         cudaFuncAttributeMaxDynamicSharedMemorySize, SMEM_BYTES);

    scan_fused_kernel<<<B, 256, SMEM_BYTES>>>(img, cap, out);
}